// round 14
// baseline (speedup 1.0000x reference)
#include <cuda_runtime.h>
#include <cuda_bf16.h>
#include <cstdint>
#include <math.h>

// Problem constants
#define BB   2
#define SS   2048
#define HID  2048
#define NH   16
#define HD   128
#define MROWS (BB*SS)   // 4096

// ---------------------------------------------------------------------------
// Warp-MMA primitives
// ---------------------------------------------------------------------------
__device__ __forceinline__ uint32_t smem_u32(const void* p) {
    uint32_t a;
    asm("{ .reg .u64 t; cvta.to.shared.u64 t, %1; cvt.u32.u64 %0, t; }"
        : "=r"(a) : "l"(p));
    return a;
}
__device__ __forceinline__ void ldm_x4(uint32_t* r, uint32_t addr) {
    asm volatile("ldmatrix.sync.aligned.m8n8.x4.shared.b16 {%0,%1,%2,%3}, [%4];"
        : "=r"(r[0]), "=r"(r[1]), "=r"(r[2]), "=r"(r[3]) : "r"(addr));
}
__device__ __forceinline__ void ldm_x4t(uint32_t* r, uint32_t addr) {
    asm volatile("ldmatrix.sync.aligned.m8n8.x4.trans.shared.b16 {%0,%1,%2,%3}, [%4];"
        : "=r"(r[0]), "=r"(r[1]), "=r"(r[2]), "=r"(r[3]) : "r"(addr));
}
__device__ __forceinline__ void mma_bf16(float* d, const uint32_t* a, const uint32_t* b) {
    asm volatile(
        "mma.sync.aligned.m16n8k16.row.col.f32.bf16.bf16.f32 "
        "{%0,%1,%2,%3}, {%4,%5,%6,%7}, {%8,%9}, {%0,%1,%2,%3};"
        : "+f"(d[0]), "+f"(d[1]), "+f"(d[2]), "+f"(d[3])
        : "r"(a[0]), "r"(a[1]), "r"(a[2]), "r"(a[3]), "r"(b[0]), "r"(b[1]));
}
__device__ __forceinline__ void cp16(uint32_t saddr, const void* g) {
    asm volatile("cp.async.cg.shared.global [%0], [%1], 16;"
        :: "r"(saddr), "l"(g));
}
#define CP_COMMIT() asm volatile("cp.async.commit_group;")
#define CP_WAIT(n)  asm volatile("cp.async.wait_group %0;" :: "n"(n))

__device__ __forceinline__ uint32_t pack2(__nv_bfloat16 a, __nv_bfloat16 b) {
    __nv_bfloat162 t(a, b);
    return *(uint32_t*)&t;
}

// ---------------------------------------------------------------------------
// Scratch (device globals; no allocation allowed)
// ---------------------------------------------------------------------------
__device__ __nv_bfloat16 g_xhi[MROWS * HID], g_xlo[MROWS * HID];
__device__ __nv_bfloat16 g_qhi[MROWS * HID], g_qlo[MROWS * HID];
__device__ __nv_bfloat16 g_khi[MROWS * HD],  g_klo[MROWS * HD];
__device__ __nv_bfloat16 g_vhi[MROWS * HD],  g_vlo[MROWS * HD];
__device__ __nv_bfloat16 g_ahi[MROWS * HID], g_alo[MROWS * HID];
__device__ __nv_bfloat16 g_wqh[HID * HID], g_wql[HID * HID];
__device__ __nv_bfloat16 g_woh[HID * HID], g_wol[HID * HID];
__device__ __nv_bfloat16 g_wkh[HID * HD],  g_wkl[HID * HD];
__device__ __nv_bfloat16 g_wvh[HID * HD],  g_wvl[HID * HD];

// ---------------------------------------------------------------------------
// Combined split: one launch covers X, Wq(scaled by qscale*log2e), Wo, Wk, Wv.
// ---------------------------------------------------------------------------
#define SPLIT_BLOCKS 16896

__global__ void split_all_kernel(
    const float* __restrict__ X,  const float* __restrict__ Wq,
    const float* __restrict__ Wk, const float* __restrict__ Wv,
    const float* __restrict__ Wo,
    __nv_bfloat16* xh, __nv_bfloat16* xl,
    __nv_bfloat16* wqh, __nv_bfloat16* wql,
    __nv_bfloat16* wkh, __nv_bfloat16* wkl,
    __nv_bfloat16* wvh, __nv_bfloat16* wvl,
    __nv_bfloat16* woh, __nv_bfloat16* wol, float qscale)
{
    int b = blockIdx.x;
    const float* in; __nv_bfloat16 *hi, *lo; int base; float sc = 1.f;
    if (b < 8192)       { in = X;  hi = xh;  lo = xl;  base = b; }
    else if (b < 12288) { in = Wq; hi = wqh; lo = wql; base = b - 8192; sc = qscale; }
    else if (b < 16384) { in = Wo; hi = woh; lo = wol; base = b - 12288; }
    else if (b < 16640) { in = Wk; hi = wkh; lo = wkl; base = b - 16384; }
    else                { in = Wv; hi = wvh; lo = wvl; base = b - 16640; }

    int i = base * 256 + threadIdx.x;
    float4 v = ((const float4*)in)[i];
    v.x *= sc; v.y *= sc; v.z *= sc; v.w *= sc;
    __nv_bfloat16 h0 = __float2bfloat16(v.x), h1 = __float2bfloat16(v.y);
    __nv_bfloat16 h2 = __float2bfloat16(v.z), h3 = __float2bfloat16(v.w);
    ((__nv_bfloat162*)hi)[2 * i + 0] = __nv_bfloat162(h0, h1);
    ((__nv_bfloat162*)hi)[2 * i + 1] = __nv_bfloat162(h2, h3);
    ((__nv_bfloat162*)lo)[2 * i + 0] = __nv_bfloat162(
        __float2bfloat16(v.x - __bfloat162float(h0)),
        __float2bfloat16(v.y - __bfloat162float(h1)));
    ((__nv_bfloat162*)lo)[2 * i + 1] = __nv_bfloat162(
        __float2bfloat16(v.z - __bfloat162float(h2)),
        __float2bfloat16(v.w - __bfloat162float(h3)));
}

// ---------------------------------------------------------------------------
// Projection GEMM body: 128x128 CTA tile, BK=32, 4 warps (warp tile 64x64),
// hi/lo 3-pass issued PASS-MAJOR (no back-to-back same-accumulator HMMA).
// 3-stage cp.async pipeline, one sync per K-step, 2 CTAs/SM.
// ---------------------------------------------------------------------------
#define PA_PITCH 80
#define PB_PITCH 272
#define PA_TILE  (128 * PA_PITCH)
#define PB_TILE  (32 * PB_PITCH)
#define PSTAGE   (2 * PA_TILE + 2 * PB_TILE)   // 37888
#define PROJ_SMEM (3 * PSTAGE)                 // 113664
#define NKC 64
#define GTHREADS 128

__device__ __forceinline__ void gemm_body(
    const __nv_bfloat16* __restrict__ Ahi, const __nv_bfloat16* __restrict__ Alo,
    const __nv_bfloat16* __restrict__ Bhi, const __nv_bfloat16* __restrict__ Blo,
    const float* __restrict__ bias, float bsc,
    float* __restrict__ Cf, __nv_bfloat16* __restrict__ Chi,
    __nv_bfloat16* __restrict__ Clo, int Nd, int m0, int n0, char* smx)
{
    const uint32_t sb = smem_u32(smx);
    const int tid  = threadIdx.x;
    const int lane = tid & 31;
    const int wid  = tid >> 5;          // 0..3
    const int wm   = wid >> 1;          // 0..1
    const int wn   = wid & 1;           // 0..1

    const __nv_bfloat16* gA_h = Ahi + ((size_t)m0 << 11);
    const __nv_bfloat16* gA_l = Alo + ((size_t)m0 << 11);

    float acc[4][8][4];
#pragma unroll
    for (int i = 0; i < 4; i++)
#pragma unroll
        for (int j = 0; j < 8; j++)
#pragma unroll
            for (int k = 0; k < 4; k++) acc[i][j][k] = 0.f;

    auto loadA = [&](uint32_t s, const __nv_bfloat16* g) {
#pragma unroll
        for (int i = 0; i < 4; i++) {
            int q = tid + (i << 7);
            int r = q >> 2, c = q & 3;
            cp16(s + r * PA_PITCH + c * 16, g + (size_t)r * 2048 + c * 8);
        }
    };
    auto loadB = [&](uint32_t s, const __nv_bfloat16* g) {
#pragma unroll
        for (int i = 0; i < 4; i++) {
            int q = tid + (i << 7);
            int r = q >> 4, c = q & 15;
            cp16(s + r * PB_PITCH + c * 16, g + (size_t)r * Nd + c * 8);
        }
    };
    auto loadStage = [&](int buf, int ks) {
        uint32_t s = sb + buf * PSTAGE;
        loadA(s,                         gA_h + (size_t)ks * 32);
        loadA(s + PA_TILE,               gA_l + (size_t)ks * 32);
        loadB(s + 2 * PA_TILE,           Bhi + (size_t)ks * 32 * Nd + n0);
        loadB(s + 2 * PA_TILE + PB_TILE, Blo + (size_t)ks * 32 * Nd + n0);
    };

    loadStage(0, 0); CP_COMMIT();
    loadStage(1, 1); CP_COMMIT();

    int buf = 0, nbuf = 2;
    for (int ks = 0; ks < NKC; ks++) {
        if (ks == NKC - 1) { CP_WAIT(0); } else { CP_WAIT(1); }
        __syncthreads();
        if (ks + 2 < NKC) { loadStage(nbuf, ks + 2); CP_COMMIT(); }

        const uint32_t st = sb + buf * PSTAGE;
        const uint32_t sAh = st, sAl = st + PA_TILE;
        const uint32_t sBh = st + 2 * PA_TILE, sBl = sBh + PB_TILE;

#pragma unroll
        for (int kk = 0; kk < 2; kk++) {
            uint32_t ah[4][4], al[4][4], bh[4][4], bl[4][4];
            const int akcol = kk * 16 + (lane >> 4) * 8;
#pragma unroll
            for (int mi = 0; mi < 4; mi++) {
                uint32_t ao = (uint32_t)((wm * 64 + mi * 16 + (lane & 15)) * PA_PITCH + akcol * 2);
                ldm_x4(ah[mi], sAh + ao);
                ldm_x4(al[mi], sAl + ao);
            }
            const int bkrow = kk * 16 + (lane & 15);
#pragma unroll
            for (int nj = 0; nj < 4; nj++) {
                int ncol = wn * 64 + nj * 16 + (lane >> 4) * 8;
                uint32_t bo = (uint32_t)(bkrow * PB_PITCH + ncol * 2);
                ldm_x4t(bh[nj], sBh + bo);
                ldm_x4t(bl[nj], sBl + bo);
            }
            // pass 1: Ahi * Bhi  (32 independent accumulators)
#pragma unroll
            for (int mi = 0; mi < 4; mi++)
#pragma unroll
                for (int ni = 0; ni < 8; ni++)
                    mma_bf16(acc[mi][ni], ah[mi], &bh[ni >> 1][(ni & 1) * 2]);
            // pass 2: Ahi * Blo
#pragma unroll
            for (int mi = 0; mi < 4; mi++)
#pragma unroll
                for (int ni = 0; ni < 8; ni++)
                    mma_bf16(acc[mi][ni], ah[mi], &bl[ni >> 1][(ni & 1) * 2]);
            // pass 3: Alo * Bhi
#pragma unroll
            for (int mi = 0; mi < 4; mi++)
#pragma unroll
                for (int ni = 0; ni < 8; ni++)
                    mma_bf16(acc[mi][ni], al[mi], &bh[ni >> 1][(ni & 1) * 2]);
        }
        buf  = (buf == 2) ? 0 : buf + 1;
        nbuf = (nbuf == 2) ? 0 : nbuf + 1;
    }

#pragma unroll
    for (int mi = 0; mi < 4; mi++) {
        int rA = m0 + wm * 64 + mi * 16 + (lane >> 2);
        int rB = rA + 8;
#pragma unroll
        for (int ni = 0; ni < 8; ni++) {
            int col = n0 + wn * 64 + ni * 8 + (lane & 3) * 2;
            float b0 = bias[col] * bsc, b1 = bias[col + 1] * bsc;
            float v0 = acc[mi][ni][0] + b0, v1 = acc[mi][ni][1] + b1;
            float v2 = acc[mi][ni][2] + b0, v3 = acc[mi][ni][3] + b1;
            if (Cf) {
                *(float2*)(Cf + (size_t)rA * Nd + col) = make_float2(v0, v1);
                *(float2*)(Cf + (size_t)rB * Nd + col) = make_float2(v2, v3);
            } else {
                __nv_bfloat16 h0 = __float2bfloat16(v0), h1 = __float2bfloat16(v1);
                __nv_bfloat16 h2 = __float2bfloat16(v2), h3 = __float2bfloat16(v3);
                *(__nv_bfloat162*)(Chi + (size_t)rA * Nd + col) = __nv_bfloat162(h0, h1);
                *(__nv_bfloat162*)(Chi + (size_t)rB * Nd + col) = __nv_bfloat162(h2, h3);
                *(__nv_bfloat162*)(Clo + (size_t)rA * Nd + col) = __nv_bfloat162(
                    __float2bfloat16(v0 - __bfloat162float(h0)),
                    __float2bfloat16(v1 - __bfloat162float(h1)));
                *(__nv_bfloat162*)(Clo + (size_t)rB * Nd + col) = __nv_bfloat162(
                    __float2bfloat16(v2 - __bfloat162float(h2)),
                    __float2bfloat16(v3 - __bfloat162float(h3)));
            }
        }
    }
}

// Fused Q+K+V projection: grid (18, 32). x<16: Q tile x; x==16: K; x==17: V.
__global__ __launch_bounds__(GTHREADS, 2) void gemm_qkv_kernel(
    const __nv_bfloat16* Ahi, const __nv_bfloat16* Alo,
    const __nv_bfloat16* Bqh, const __nv_bfloat16* Bql, const float* bq, float bqsc,
    __nv_bfloat16* Qh, __nv_bfloat16* Ql,
    const __nv_bfloat16* Bkh, const __nv_bfloat16* Bkl, const float* bk,
    __nv_bfloat16* Kh, __nv_bfloat16* Kl,
    const __nv_bfloat16* Bvh, const __nv_bfloat16* Bvl, const float* bv,
    __nv_bfloat16* Vh, __nv_bfloat16* Vl)
{
    extern __shared__ char smx[];
    const int x = blockIdx.x, m0 = blockIdx.y << 7;
    if (x < 16)
        gemm_body(Ahi, Alo, Bqh, Bql, bq, bqsc, nullptr, Qh, Ql, HID, m0, x << 7, smx);
    else if (x == 16)
        gemm_body(Ahi, Alo, Bkh, Bkl, bk, 1.f, nullptr, Kh, Kl, HD, m0, 0, smx);
    else
        gemm_body(Ahi, Alo, Bvh, Bvl, bv, 1.f, nullptr, Vh, Vl, HD, m0, 0, smx);
}

// O projection (f32 output)
__global__ __launch_bounds__(GTHREADS, 2) void gemm_o_kernel(
    const __nv_bfloat16* Ahi, const __nv_bfloat16* Alo,
    const __nv_bfloat16* Bhi, const __nv_bfloat16* Blo,
    const float* bias, float* Cf)
{
    extern __shared__ char smx[];
    gemm_body(Ahi, Alo, Bhi, Blo, bias, 1.f, Cf, nullptr, nullptr, HID,
              blockIdx.y << 7, blockIdx.x << 7, smx);
}

// ---------------------------------------------------------------------------
// Flash attention (MQA): 4-warp CTA, 64 q-rows, Q register-resident,
// 32-key KV tiles in a 3-stage ring. Pass-major MMA issue. 2 CTAs/SM.
// ---------------------------------------------------------------------------
#define FQP 272
#define KSTG 34816                   // one stage: KH,KL,VH,VL @ 8704 each
#define FLASH_SMEM (3 * KSTG)        // 104448
#define NT2 (SS / 32)                // 64 tiles

__global__ __launch_bounds__(128, 2) void mqa_mma_kernel(
    const __nv_bfloat16* __restrict__ qhi, const __nv_bfloat16* __restrict__ qlo,
    const __nv_bfloat16* __restrict__ khi, const __nv_bfloat16* __restrict__ klo,
    const __nv_bfloat16* __restrict__ vhi, const __nv_bfloat16* __restrict__ vlo,
    __nv_bfloat16* __restrict__ ohi, __nv_bfloat16* __restrict__ olo)
{
    extern __shared__ char smx[];
    const uint32_t sb = smem_u32(smx);
    const int tid  = threadIdx.x;
    const int lane = tid & 31;
    const int wid  = tid >> 5;          // 0..3
    const int wr   = wid << 4;          // warp row base 0..48
    const int m0   = blockIdx.x << 6;   // 64 rows per CTA
    const int h    = blockIdx.y;
    const int bb   = blockIdx.z;

    auto loadQ = [&](uint32_t s, const __nv_bfloat16* g) {
#pragma unroll
        for (int i = 0; i < 8; i++) {
            int q = tid + (i << 7);
            int r = q >> 4, c = q & 15;
            cp16(s + r * FQP + c * 16, g + (size_t)r * HID + c * 8);
        }
    };
    auto loadKV32 = [&](uint32_t s, const __nv_bfloat16* g) {
#pragma unroll
        for (int i = 0; i < 4; i++) {
            int q = tid + (i << 7);
            int r = q >> 4, c = q & 15;
            cp16(s + r * FQP + c * 16, g + (size_t)r * HD + c * 8);
        }
    };
    auto loadStage = [&](int buf, int t) {
        uint32_t s = sb + buf * KSTG;
        const size_t kvb = ((size_t)(bb * SS + t * 32)) * HD;
        loadKV32(s,            khi + kvb);
        loadKV32(s + 8704,     klo + kvb);
        loadKV32(s + 2 * 8704, vhi + kvb);
        loadKV32(s + 3 * 8704, vlo + kvb);
    };

    // ---- prologue: load Q into smem, hoist fragments to registers ----
    const size_t qbase = ((size_t)(bb * SS + m0)) * HID + h * HD;
    loadQ(sb, qhi + qbase);
    loadQ(sb + 17408, qlo + qbase);
    CP_COMMIT();
    CP_WAIT(0);
    __syncthreads();

    uint32_t qfh[8][4], qfl[8][4];
#pragma unroll
    for (int kk = 0; kk < 8; kk++) {
        uint32_t qo = (uint32_t)((wr + (lane & 15)) * FQP + (kk * 16 + (lane >> 4) * 8) * 2);
        ldm_x4(qfh[kk], sb + qo);
        ldm_x4(qfl[kk], sb + 17408 + qo);
    }
    __syncthreads();   // all warps hoisted Q before KV overwrites it

    loadStage(0, 0); CP_COMMIT();
    loadStage(1, 1); CP_COMMIT();

    float mrunA = -INFINITY, mrunB = -INFINITY, lrunA = 0.f, lrunB = 0.f;
    float oacc[16][4];
#pragma unroll
    for (int i = 0; i < 16; i++)
#pragma unroll
        for (int k = 0; k < 4; k++) oacc[i][k] = 0.f;

    int buf = 0, nbuf = 2;
    for (int t = 0; t < NT2; t++) {
        if (t == NT2 - 1) { CP_WAIT(0); } else { CP_WAIT(1); }
        __syncthreads();
        if (t + 2 < NT2) { loadStage(nbuf, t + 2); CP_COMMIT(); }

        const uint32_t st = sb + buf * KSTG;
        const uint32_t sKh = st, sKl = st + 8704;
        const uint32_t sVh = st + 2 * 8704, sVl = st + 3 * 8704;

        // ---- S = Q @ K^T : warp tile m16 x n32, pass-major ----
        float sacc[4][4];
#pragma unroll
        for (int i = 0; i < 4; i++)
#pragma unroll
            for (int k = 0; k < 4; k++) sacc[i][k] = 0.f;

#pragma unroll
        for (int kk = 0; kk < 8; kk++) {
            const int kcol = kk * 16 + ((lane >> 3) & 1) * 8;
            uint32_t kh4[2][4], kl4[2][4];
#pragma unroll
            for (int nj = 0; nj < 2; nj++) {
                int keyrow = nj * 16 + (lane >> 4) * 8 + (lane & 7);
                uint32_t ko = (uint32_t)(keyrow * FQP + kcol * 2);
                ldm_x4(kh4[nj], sKh + ko);
                ldm_x4(kl4[nj], sKl + ko);
            }
            // pass hh (4 independent accs)
            mma_bf16(sacc[0], qfh[kk], &kh4[0][0]);
            mma_bf16(sacc[1], qfh[kk], &kh4[0][2]);
            mma_bf16(sacc[2], qfh[kk], &kh4[1][0]);
            mma_bf16(sacc[3], qfh[kk], &kh4[1][2]);
            // pass hl
            mma_bf16(sacc[0], qfh[kk], &kl4[0][0]);
            mma_bf16(sacc[1], qfh[kk], &kl4[0][2]);
            mma_bf16(sacc[2], qfh[kk], &kl4[1][0]);
            mma_bf16(sacc[3], qfh[kk], &kl4[1][2]);
            // pass lh
            mma_bf16(sacc[0], qfl[kk], &kh4[0][0]);
            mma_bf16(sacc[1], qfl[kk], &kh4[0][2]);
            mma_bf16(sacc[2], qfl[kk], &kh4[1][0]);
            mma_bf16(sacc[3], qfl[kk], &kh4[1][2]);
        }

        // ---- fragment-resident online softmax (exp2 domain) ----
        float mA = -INFINITY, mB = -INFINITY;
#pragma unroll
        for (int nt = 0; nt < 4; nt++) {
            mA = fmaxf(mA, fmaxf(sacc[nt][0], sacc[nt][1]));
            mB = fmaxf(mB, fmaxf(sacc[nt][2], sacc[nt][3]));
        }
        mA = fmaxf(mA, __shfl_xor_sync(0xffffffffu, mA, 1));
        mA = fmaxf(mA, __shfl_xor_sync(0xffffffffu, mA, 2));
        mB = fmaxf(mB, __shfl_xor_sync(0xffffffffu, mB, 1));
        mB = fmaxf(mB, __shfl_xor_sync(0xffffffffu, mB, 2));

        float mnewA = fmaxf(mrunA, mA), mnewB = fmaxf(mrunB, mB);
        float alphaA = exp2f(mrunA - mnewA), alphaB = exp2f(mrunB - mnewB);
        mrunA = mnewA; mrunB = mnewB;

        uint32_t pfh[2][4], pfl[2][4];
        float sumA = 0.f, sumB = 0.f;
#pragma unroll
        for (int nt = 0; nt < 4; nt++) {
            float p0 = exp2f(sacc[nt][0] - mnewA);
            float p1 = exp2f(sacc[nt][1] - mnewA);
            float p2 = exp2f(sacc[nt][2] - mnewB);
            float p3 = exp2f(sacc[nt][3] - mnewB);
            sumA += p0 + p1; sumB += p2 + p3;
            __nv_bfloat16 h0 = __float2bfloat16(p0), h1 = __float2bfloat16(p1);
            __nv_bfloat16 h2 = __float2bfloat16(p2), h3 = __float2bfloat16(p3);
            int kk2 = nt >> 1, sl = (nt & 1) * 2;
            pfh[kk2][sl]     = pack2(h0, h1);
            pfh[kk2][sl + 1] = pack2(h2, h3);
            pfl[kk2][sl]     = pack2(__float2bfloat16(p0 - __bfloat162float(h0)),
                                     __float2bfloat16(p1 - __bfloat162float(h1)));
            pfl[kk2][sl + 1] = pack2(__float2bfloat16(p2 - __bfloat162float(h2)),
                                     __float2bfloat16(p3 - __bfloat162float(h3)));
        }
        sumA += __shfl_xor_sync(0xffffffffu, sumA, 1);
        sumA += __shfl_xor_sync(0xffffffffu, sumA, 2);
        sumB += __shfl_xor_sync(0xffffffffu, sumB, 1);
        sumB += __shfl_xor_sync(0xffffffffu, sumB, 2);
        lrunA = lrunA * alphaA + sumA;
        lrunB = lrunB * alphaB + sumB;

#pragma unroll
        for (int nt = 0; nt < 16; nt++) {
            oacc[nt][0] *= alphaA; oacc[nt][1] *= alphaA;
            oacc[nt][2] *= alphaB; oacc[nt][3] *= alphaB;
        }

        // ---- O += P @ V : dj pairs, pass-major over 4 accs ----
#pragma unroll
        for (int kk2 = 0; kk2 < 2; kk2++) {
            const int keyrow = kk2 * 16 + (lane & 15);
#pragma unroll
            for (int djp = 0; djp < 4; djp++) {
                uint32_t vh4[2][4], vl4[2][4];
#pragma unroll
                for (int e = 0; e < 2; e++) {
                    int dcol = (djp * 2 + e) * 16 + (lane >> 4) * 8;
                    uint32_t vo = (uint32_t)(keyrow * FQP + dcol * 2);
                    ldm_x4t(vh4[e], sVh + vo);
                    ldm_x4t(vl4[e], sVl + vo);
                }
                float* o0 = oacc[4 * djp + 0];
                float* o1 = oacc[4 * djp + 1];
                float* o2 = oacc[4 * djp + 2];
                float* o3 = oacc[4 * djp + 3];
                // pass hh
                mma_bf16(o0, pfh[kk2], &vh4[0][0]);
                mma_bf16(o1, pfh[kk2], &vh4[0][2]);
                mma_bf16(o2, pfh[kk2], &vh4[1][0]);
                mma_bf16(o3, pfh[kk2], &vh4[1][2]);
                // pass hl
                mma_bf16(o0, pfh[kk2], &vl4[0][0]);
                mma_bf16(o1, pfh[kk2], &vl4[0][2]);
                mma_bf16(o2, pfh[kk2], &vl4[1][0]);
                mma_bf16(o3, pfh[kk2], &vl4[1][2]);
                // pass lh
                mma_bf16(o0, pfl[kk2], &vh4[0][0]);
                mma_bf16(o1, pfl[kk2], &vh4[0][2]);
                mma_bf16(o2, pfl[kk2], &vh4[1][0]);
                mma_bf16(o3, pfl[kk2], &vh4[1][2]);
            }
        }

        buf  = (buf == 2) ? 0 : buf + 1;
        nbuf = (nbuf == 2) ? 0 : nbuf + 1;
    }

    // ---- epilogue ----
    const float invA = 1.f / lrunA, invB = 1.f / lrunB;
    int rA = wr + (lane >> 2), rB = rA + 8;
    size_t gA = ((size_t)(bb * SS + m0 + rA)) * HID + h * HD;
    size_t gB = ((size_t)(bb * SS + m0 + rB)) * HID + h * HD;
#pragma unroll
    for (int nt = 0; nt < 16; nt++) {
        int col = nt * 8 + (lane & 3) * 2;
        float v0 = oacc[nt][0] * invA, v1 = oacc[nt][1] * invA;
        float v2 = oacc[nt][2] * invB, v3 = oacc[nt][3] * invB;
        __nv_bfloat16 h0 = __float2bfloat16(v0), h1 = __float2bfloat16(v1);
        __nv_bfloat16 h2 = __float2bfloat16(v2), h3 = __float2bfloat16(v3);
        *(__nv_bfloat162*)(ohi + gA + col) = __nv_bfloat162(h0, h1);
        *(__nv_bfloat162*)(ohi + gB + col) = __nv_bfloat162(h2, h3);
        *(__nv_bfloat162*)(olo + gA + col) = __nv_bfloat162(
            __float2bfloat16(v0 - __bfloat162float(h0)),
            __float2bfloat16(v1 - __bfloat162float(h1)));
        *(__nv_bfloat162*)(olo + gB + col) = __nv_bfloat162(
            __float2bfloat16(v2 - __bfloat162float(h2)),
            __float2bfloat16(v3 - __bfloat162float(h3)));
    }
}

// ---------------------------------------------------------------------------
// Launch
// ---------------------------------------------------------------------------
extern "C" void kernel_launch(void* const* d_in, const int* in_sizes, int n_in,
                              void* d_out, int out_size)
{
    const float* X  = (const float*)d_in[0];
    const float* Wq = (const float*)d_in[1];
    const float* bq = (const float*)d_in[2];
    const float* Wk = (const float*)d_in[3];
    const float* bk = (const float*)d_in[4];
    const float* Wv = (const float*)d_in[5];
    const float* bv = (const float*)d_in[6];
    const float* Wo = (const float*)d_in[7];
    const float* bo = (const float*)d_in[8];
    float* out = (float*)d_out;

    // 1/sqrt(128) * log2(e): softmax runs in exp2 domain
    const float qscale2 = 0.127517432f;

    __nv_bfloat16 *xh, *xl, *qh, *ql, *kh, *kl, *vh, *vl, *ah, *al;
    __nv_bfloat16 *wqh, *wql, *wkh, *wkl, *wvh, *wvl, *woh, *wol;
    cudaGetSymbolAddress((void**)&xh, g_xhi);  cudaGetSymbolAddress((void**)&xl, g_xlo);
    cudaGetSymbolAddress((void**)&qh, g_qhi);  cudaGetSymbolAddress((void**)&ql, g_qlo);
    cudaGetSymbolAddress((void**)&kh, g_khi);  cudaGetSymbolAddress((void**)&kl, g_klo);
    cudaGetSymbolAddress((void**)&vh, g_vhi);  cudaGetSymbolAddress((void**)&vl, g_vlo);
    cudaGetSymbolAddress((void**)&ah, g_ahi);  cudaGetSymbolAddress((void**)&al, g_alo);
    cudaGetSymbolAddress((void**)&wqh, g_wqh); cudaGetSymbolAddress((void**)&wql, g_wql);
    cudaGetSymbolAddress((void**)&wkh, g_wkh); cudaGetSymbolAddress((void**)&wkl, g_wkl);
    cudaGetSymbolAddress((void**)&wvh, g_wvh); cudaGetSymbolAddress((void**)&wvl, g_wvl);
    cudaGetSymbolAddress((void**)&woh, g_woh); cudaGetSymbolAddress((void**)&wol, g_wol);

    cudaFuncSetAttribute(gemm_qkv_kernel,
                         cudaFuncAttributeMaxDynamicSharedMemorySize, PROJ_SMEM);
    cudaFuncSetAttribute(gemm_o_kernel,
                         cudaFuncAttributeMaxDynamicSharedMemorySize, PROJ_SMEM);
    cudaFuncSetAttribute(mqa_mma_kernel,
                         cudaFuncAttributeMaxDynamicSharedMemorySize, FLASH_SMEM);

    // 1. all splits in one launch (scale folded into Wq)
    split_all_kernel<<<SPLIT_BLOCKS, 256>>>(
        X, Wq, Wk, Wv, Wo,
        xh, xl, wqh, wql, wkh, wkl, wvh, wvl, woh, wol, qscale2);

    // 2. fused Q+K+V projection (one launch, 576 CTAs, 128 threads)
    gemm_qkv_kernel<<<dim3(18, MROWS / 128), GTHREADS, PROJ_SMEM>>>(
        xh, xl,
        wqh, wql, bq, qscale2, qh, ql,
        wkh, wkl, bk, kh, kl,
        wvh, wvl, bv, vh, vl);

    // 3. flash attention (4-warp CTAs, 2/SM, 32-key tiles)
    mqa_mma_kernel<<<dim3(SS / 64, NH, BB), 128, FLASH_SMEM>>>(
        qh, ql, kh, kl, vh, vl, ah, al);

    // 4. output projection
    gemm_o_kernel<<<dim3(HID / 128, MROWS / 128), GTHREADS, PROJ_SMEM>>>(
        ah, al, woh, wol, bo, out);
}

// round 16
// speedup vs baseline: 1.0261x; 1.0261x over previous
#include <cuda_runtime.h>
#include <cuda_bf16.h>
#include <cstdint>
#include <math.h>

// Problem constants
#define BB   2
#define SS   2048
#define HID  2048
#define NH   16
#define HD   128
#define MROWS (BB*SS)   // 4096

// ---------------------------------------------------------------------------
// Warp-MMA primitives
// ---------------------------------------------------------------------------
__device__ __forceinline__ uint32_t smem_u32(const void* p) {
    uint32_t a;
    asm("{ .reg .u64 t; cvta.to.shared.u64 t, %1; cvt.u32.u64 %0, t; }"
        : "=r"(a) : "l"(p));
    return a;
}
__device__ __forceinline__ void ldm_x4(uint32_t* r, uint32_t addr) {
    asm volatile("ldmatrix.sync.aligned.m8n8.x4.shared.b16 {%0,%1,%2,%3}, [%4];"
        : "=r"(r[0]), "=r"(r[1]), "=r"(r[2]), "=r"(r[3]) : "r"(addr));
}
__device__ __forceinline__ void ldm_x4t(uint32_t* r, uint32_t addr) {
    asm volatile("ldmatrix.sync.aligned.m8n8.x4.trans.shared.b16 {%0,%1,%2,%3}, [%4];"
        : "=r"(r[0]), "=r"(r[1]), "=r"(r[2]), "=r"(r[3]) : "r"(addr));
}
// NOTE: non-volatile — pure register op; lets ptxas interleave HMMA with LDSM.
__device__ __forceinline__ void mma_bf16(float* d, const uint32_t* a, const uint32_t* b) {
    asm("mma.sync.aligned.m16n8k16.row.col.f32.bf16.bf16.f32 "
        "{%0,%1,%2,%3}, {%4,%5,%6,%7}, {%8,%9}, {%0,%1,%2,%3};"
        : "+f"(d[0]), "+f"(d[1]), "+f"(d[2]), "+f"(d[3])
        : "r"(a[0]), "r"(a[1]), "r"(a[2]), "r"(a[3]), "r"(b[0]), "r"(b[1]));
}
__device__ __forceinline__ void cp16(uint32_t saddr, const void* g) {
    asm volatile("cp.async.cg.shared.global [%0], [%1], 16;"
        :: "r"(saddr), "l"(g));
}
#define CP_COMMIT() asm volatile("cp.async.commit_group;")
#define CP_WAIT(n)  asm volatile("cp.async.wait_group %0;" :: "n"(n))

__device__ __forceinline__ uint32_t pack2(__nv_bfloat16 a, __nv_bfloat16 b) {
    __nv_bfloat162 t(a, b);
    return *(uint32_t*)&t;
}

// ---------------------------------------------------------------------------
// Scratch (device globals; no allocation allowed)
// ---------------------------------------------------------------------------
__device__ __nv_bfloat16 g_xhi[MROWS * HID], g_xlo[MROWS * HID];
__device__ __nv_bfloat16 g_qhi[MROWS * HID], g_qlo[MROWS * HID];
__device__ __nv_bfloat16 g_khi[MROWS * HD],  g_klo[MROWS * HD];
__device__ __nv_bfloat16 g_vhi[MROWS * HD],  g_vlo[MROWS * HD];
__device__ __nv_bfloat16 g_ahi[MROWS * HID], g_alo[MROWS * HID];
__device__ __nv_bfloat16 g_wqh[HID * HID], g_wql[HID * HID];
__device__ __nv_bfloat16 g_woh[HID * HID], g_wol[HID * HID];
__device__ __nv_bfloat16 g_wkh[HID * HD],  g_wkl[HID * HD];
__device__ __nv_bfloat16 g_wvh[HID * HD],  g_wvl[HID * HD];

// ---------------------------------------------------------------------------
// Combined split: one launch covers X, Wq(scaled by qscale*log2e), Wo, Wk, Wv.
// ---------------------------------------------------------------------------
#define SPLIT_BLOCKS 16896

__global__ void split_all_kernel(
    const float* __restrict__ X,  const float* __restrict__ Wq,
    const float* __restrict__ Wk, const float* __restrict__ Wv,
    const float* __restrict__ Wo,
    __nv_bfloat16* xh, __nv_bfloat16* xl,
    __nv_bfloat16* wqh, __nv_bfloat16* wql,
    __nv_bfloat16* wkh, __nv_bfloat16* wkl,
    __nv_bfloat16* wvh, __nv_bfloat16* wvl,
    __nv_bfloat16* woh, __nv_bfloat16* wol, float qscale)
{
    int b = blockIdx.x;
    const float* in; __nv_bfloat16 *hi, *lo; int base; float sc = 1.f;
    if (b < 8192)       { in = X;  hi = xh;  lo = xl;  base = b; }
    else if (b < 12288) { in = Wq; hi = wqh; lo = wql; base = b - 8192; sc = qscale; }
    else if (b < 16384) { in = Wo; hi = woh; lo = wol; base = b - 12288; }
    else if (b < 16640) { in = Wk; hi = wkh; lo = wkl; base = b - 16384; }
    else                { in = Wv; hi = wvh; lo = wvl; base = b - 16640; }

    int i = base * 256 + threadIdx.x;
    float4 v = ((const float4*)in)[i];
    v.x *= sc; v.y *= sc; v.z *= sc; v.w *= sc;
    __nv_bfloat16 h0 = __float2bfloat16(v.x), h1 = __float2bfloat16(v.y);
    __nv_bfloat16 h2 = __float2bfloat16(v.z), h3 = __float2bfloat16(v.w);
    ((__nv_bfloat162*)hi)[2 * i + 0] = __nv_bfloat162(h0, h1);
    ((__nv_bfloat162*)hi)[2 * i + 1] = __nv_bfloat162(h2, h3);
    ((__nv_bfloat162*)lo)[2 * i + 0] = __nv_bfloat162(
        __float2bfloat16(v.x - __bfloat162float(h0)),
        __float2bfloat16(v.y - __bfloat162float(h1)));
    ((__nv_bfloat162*)lo)[2 * i + 1] = __nv_bfloat162(
        __float2bfloat16(v.z - __bfloat162float(h2)),
        __float2bfloat16(v.w - __bfloat162float(h3)));
}

// ---------------------------------------------------------------------------
// Projection GEMM body: 128x128 CTA tile, BK=32, 4 warps (warp tile 64x64),
// hi/lo 3-pass, 3-stage cp.async pipeline, one sync per K-step, 2 CTAs/SM.
// ---------------------------------------------------------------------------
#define PA_PITCH 80
#define PB_PITCH 272
#define PA_TILE  (128 * PA_PITCH)
#define PB_TILE  (32 * PB_PITCH)
#define PSTAGE   (2 * PA_TILE + 2 * PB_TILE)   // 37888
#define PROJ_SMEM (3 * PSTAGE)                 // 113664
#define NKC 64
#define GTHREADS 128

__device__ __forceinline__ void gemm_body(
    const __nv_bfloat16* __restrict__ Ahi, const __nv_bfloat16* __restrict__ Alo,
    const __nv_bfloat16* __restrict__ Bhi, const __nv_bfloat16* __restrict__ Blo,
    const float* __restrict__ bias, float bsc,
    float* __restrict__ Cf, __nv_bfloat16* __restrict__ Chi,
    __nv_bfloat16* __restrict__ Clo, int Nd, int m0, int n0, char* smx)
{
    const uint32_t sb = smem_u32(smx);
    const int tid  = threadIdx.x;
    const int lane = tid & 31;
    const int wid  = tid >> 5;          // 0..3
    const int wm   = wid >> 1;          // 0..1
    const int wn   = wid & 1;           // 0..1

    const __nv_bfloat16* gA_h = Ahi + ((size_t)m0 << 11);
    const __nv_bfloat16* gA_l = Alo + ((size_t)m0 << 11);

    float acc[4][8][4];
#pragma unroll
    for (int i = 0; i < 4; i++)
#pragma unroll
        for (int j = 0; j < 8; j++)
#pragma unroll
            for (int k = 0; k < 4; k++) acc[i][j][k] = 0.f;

    auto loadA = [&](uint32_t s, const __nv_bfloat16* g) {
#pragma unroll
        for (int i = 0; i < 4; i++) {
            int q = tid + (i << 7);
            int r = q >> 2, c = q & 3;
            cp16(s + r * PA_PITCH + c * 16, g + (size_t)r * 2048 + c * 8);
        }
    };
    auto loadB = [&](uint32_t s, const __nv_bfloat16* g) {
#pragma unroll
        for (int i = 0; i < 4; i++) {
            int q = tid + (i << 7);
            int r = q >> 4, c = q & 15;
            cp16(s + r * PB_PITCH + c * 16, g + (size_t)r * Nd + c * 8);
        }
    };
    auto loadStage = [&](int buf, int ks) {
        uint32_t s = sb + buf * PSTAGE;
        loadA(s,                         gA_h + (size_t)ks * 32);
        loadA(s + PA_TILE,               gA_l + (size_t)ks * 32);
        loadB(s + 2 * PA_TILE,           Bhi + (size_t)ks * 32 * Nd + n0);
        loadB(s + 2 * PA_TILE + PB_TILE, Blo + (size_t)ks * 32 * Nd + n0);
    };

    loadStage(0, 0); CP_COMMIT();
    loadStage(1, 1); CP_COMMIT();

    int buf = 0, nbuf = 2;
    for (int ks = 0; ks < NKC; ks++) {
        if (ks == NKC - 1) { CP_WAIT(0); } else { CP_WAIT(1); }
        __syncthreads();
        if (ks + 2 < NKC) { loadStage(nbuf, ks + 2); CP_COMMIT(); }

        const uint32_t st = sb + buf * PSTAGE;
        const uint32_t sAh = st, sAl = st + PA_TILE;
        const uint32_t sBh = st + 2 * PA_TILE, sBl = sBh + PB_TILE;

#pragma unroll
        for (int kk = 0; kk < 2; kk++) {
            uint32_t ah[4][4], al[4][4], bh[4][4], bl[4][4];
            const int akcol = kk * 16 + (lane >> 4) * 8;
#pragma unroll
            for (int mi = 0; mi < 4; mi++) {
                uint32_t ao = (uint32_t)((wm * 64 + mi * 16 + (lane & 15)) * PA_PITCH + akcol * 2);
                ldm_x4(ah[mi], sAh + ao);
                ldm_x4(al[mi], sAl + ao);
            }
            const int bkrow = kk * 16 + (lane & 15);
#pragma unroll
            for (int nj = 0; nj < 4; nj++) {
                int ncol = wn * 64 + nj * 16 + (lane >> 4) * 8;
                uint32_t bo = (uint32_t)(bkrow * PB_PITCH + ncol * 2);
                ldm_x4t(bh[nj], sBh + bo);
                ldm_x4t(bl[nj], sBl + bo);
            }
#pragma unroll
            for (int mi = 0; mi < 4; mi++)
#pragma unroll
                for (int ni = 0; ni < 8; ni++)
                    mma_bf16(acc[mi][ni], ah[mi], &bh[ni >> 1][(ni & 1) * 2]);
#pragma unroll
            for (int mi = 0; mi < 4; mi++)
#pragma unroll
                for (int ni = 0; ni < 8; ni++)
                    mma_bf16(acc[mi][ni], ah[mi], &bl[ni >> 1][(ni & 1) * 2]);
#pragma unroll
            for (int mi = 0; mi < 4; mi++)
#pragma unroll
                for (int ni = 0; ni < 8; ni++)
                    mma_bf16(acc[mi][ni], al[mi], &bh[ni >> 1][(ni & 1) * 2]);
        }
        buf  = (buf == 2) ? 0 : buf + 1;
        nbuf = (nbuf == 2) ? 0 : nbuf + 1;
    }

#pragma unroll
    for (int mi = 0; mi < 4; mi++) {
        int rA = m0 + wm * 64 + mi * 16 + (lane >> 2);
        int rB = rA + 8;
#pragma unroll
        for (int ni = 0; ni < 8; ni++) {
            int col = n0 + wn * 64 + ni * 8 + (lane & 3) * 2;
            float b0 = bias[col] * bsc, b1 = bias[col + 1] * bsc;
            float v0 = acc[mi][ni][0] + b0, v1 = acc[mi][ni][1] + b1;
            float v2 = acc[mi][ni][2] + b0, v3 = acc[mi][ni][3] + b1;
            if (Cf) {
                *(float2*)(Cf + (size_t)rA * Nd + col) = make_float2(v0, v1);
                *(float2*)(Cf + (size_t)rB * Nd + col) = make_float2(v2, v3);
            } else {
                __nv_bfloat16 h0 = __float2bfloat16(v0), h1 = __float2bfloat16(v1);
                __nv_bfloat16 h2 = __float2bfloat16(v2), h3 = __float2bfloat16(v3);
                *(__nv_bfloat162*)(Chi + (size_t)rA * Nd + col) = __nv_bfloat162(h0, h1);
                *(__nv_bfloat162*)(Chi + (size_t)rB * Nd + col) = __nv_bfloat162(h2, h3);
                *(__nv_bfloat162*)(Clo + (size_t)rA * Nd + col) = __nv_bfloat162(
                    __float2bfloat16(v0 - __bfloat162float(h0)),
                    __float2bfloat16(v1 - __bfloat162float(h1)));
                *(__nv_bfloat162*)(Clo + (size_t)rB * Nd + col) = __nv_bfloat162(
                    __float2bfloat16(v2 - __bfloat162float(h2)),
                    __float2bfloat16(v3 - __bfloat162float(h3)));
            }
        }
    }
}

// Fused Q+K+V projection: grid (18, 32). x<16: Q tile x; x==16: K; x==17: V.
__global__ __launch_bounds__(GTHREADS, 2) void gemm_qkv_kernel(
    const __nv_bfloat16* Ahi, const __nv_bfloat16* Alo,
    const __nv_bfloat16* Bqh, const __nv_bfloat16* Bql, const float* bq, float bqsc,
    __nv_bfloat16* Qh, __nv_bfloat16* Ql,
    const __nv_bfloat16* Bkh, const __nv_bfloat16* Bkl, const float* bk,
    __nv_bfloat16* Kh, __nv_bfloat16* Kl,
    const __nv_bfloat16* Bvh, const __nv_bfloat16* Bvl, const float* bv,
    __nv_bfloat16* Vh, __nv_bfloat16* Vl)
{
    extern __shared__ char smx[];
    const int x = blockIdx.x, m0 = blockIdx.y << 7;
    if (x < 16)
        gemm_body(Ahi, Alo, Bqh, Bql, bq, bqsc, nullptr, Qh, Ql, HID, m0, x << 7, smx);
    else if (x == 16)
        gemm_body(Ahi, Alo, Bkh, Bkl, bk, 1.f, nullptr, Kh, Kl, HD, m0, 0, smx);
    else
        gemm_body(Ahi, Alo, Bvh, Bvl, bv, 1.f, nullptr, Vh, Vl, HD, m0, 0, smx);
}

// O projection (f32 output)
__global__ __launch_bounds__(GTHREADS, 2) void gemm_o_kernel(
    const __nv_bfloat16* Ahi, const __nv_bfloat16* Alo,
    const __nv_bfloat16* Bhi, const __nv_bfloat16* Blo,
    const float* bias, float* Cf)
{
    extern __shared__ char smx[];
    gemm_body(Ahi, Alo, Bhi, Blo, bias, 1.f, Cf, nullptr, nullptr, HID,
              blockIdx.y << 7, blockIdx.x << 7, smx);
}

// ---------------------------------------------------------------------------
// Flash attention (MQA): 4-warp CTA, 64 q-rows, Q register-resident,
// 32-key KV tiles in a 3-stage ring. Deferred l-reduction. 2 CTAs/SM.
// ---------------------------------------------------------------------------
#define FQP 272
#define KSTG 34816                   // one stage: KH,KL,VH,VL @ 8704 each
#define FLASH_SMEM (3 * KSTG)        // 104448
#define NT2 (SS / 32)                // 64 tiles

__global__ __launch_bounds__(128, 2) void mqa_mma_kernel(
    const __nv_bfloat16* __restrict__ qhi, const __nv_bfloat16* __restrict__ qlo,
    const __nv_bfloat16* __restrict__ khi, const __nv_bfloat16* __restrict__ klo,
    const __nv_bfloat16* __restrict__ vhi, const __nv_bfloat16* __restrict__ vlo,
    __nv_bfloat16* __restrict__ ohi, __nv_bfloat16* __restrict__ olo)
{
    extern __shared__ char smx[];
    const uint32_t sb = smem_u32(smx);
    const int tid  = threadIdx.x;
    const int lane = tid & 31;
    const int wid  = tid >> 5;          // 0..3
    const int wr   = wid << 4;          // warp row base 0..48
    const int m0   = blockIdx.x << 6;   // 64 rows per CTA
    const int h    = blockIdx.y;
    const int bb   = blockIdx.z;

    auto loadQ = [&](uint32_t s, const __nv_bfloat16* g) {
#pragma unroll
        for (int i = 0; i < 8; i++) {
            int q = tid + (i << 7);
            int r = q >> 4, c = q & 15;
            cp16(s + r * FQP + c * 16, g + (size_t)r * HID + c * 8);
        }
    };
    auto loadKV32 = [&](uint32_t s, const __nv_bfloat16* g) {
#pragma unroll
        for (int i = 0; i < 4; i++) {
            int q = tid + (i << 7);
            int r = q >> 4, c = q & 15;
            cp16(s + r * FQP + c * 16, g + (size_t)r * HD + c * 8);
        }
    };
    auto loadStage = [&](int buf, int t) {
        uint32_t s = sb + buf * KSTG;
        const size_t kvb = ((size_t)(bb * SS + t * 32)) * HD;
        loadKV32(s,            khi + kvb);
        loadKV32(s + 8704,     klo + kvb);
        loadKV32(s + 2 * 8704, vhi + kvb);
        loadKV32(s + 3 * 8704, vlo + kvb);
    };

    // ---- prologue: load Q into smem, hoist fragments to registers ----
    const size_t qbase = ((size_t)(bb * SS + m0)) * HID + h * HD;
    loadQ(sb, qhi + qbase);
    loadQ(sb + 17408, qlo + qbase);
    CP_COMMIT();
    CP_WAIT(0);
    __syncthreads();

    uint32_t qfh[8][4], qfl[8][4];
#pragma unroll
    for (int kk = 0; kk < 8; kk++) {
        uint32_t qo = (uint32_t)((wr + (lane & 15)) * FQP + (kk * 16 + (lane >> 4) * 8) * 2);
        ldm_x4(qfh[kk], sb + qo);
        ldm_x4(qfl[kk], sb + 17408 + qo);
    }
    __syncthreads();   // all warps hoisted Q before KV overwrites it

    loadStage(0, 0); CP_COMMIT();
    loadStage(1, 1); CP_COMMIT();

    float mrunA = -INFINITY, mrunB = -INFINITY;
    float lrunA = 0.f, lrunB = 0.f;    // per-lane partial (reduced at epilogue)
    float oacc[16][4];
#pragma unroll
    for (int i = 0; i < 16; i++)
#pragma unroll
        for (int k = 0; k < 4; k++) oacc[i][k] = 0.f;

    int buf = 0, nbuf = 2;
    for (int t = 0; t < NT2; t++) {
        if (t == NT2 - 1) { CP_WAIT(0); } else { CP_WAIT(1); }
        __syncthreads();
        if (t + 2 < NT2) { loadStage(nbuf, t + 2); CP_COMMIT(); }

        const uint32_t st = sb + buf * KSTG;
        const uint32_t sKh = st, sKl = st + 8704;
        const uint32_t sVh = st + 2 * 8704, sVl = st + 3 * 8704;

        // ---- S = Q @ K^T : warp tile m16 x n32 ----
        float sacc[4][4];
#pragma unroll
        for (int i = 0; i < 4; i++)
#pragma unroll
            for (int k = 0; k < 4; k++) sacc[i][k] = 0.f;

#pragma unroll
        for (int kk = 0; kk < 8; kk++) {
            const int kcol = kk * 16 + ((lane >> 3) & 1) * 8;
            uint32_t kh4[2][4], kl4[2][4];
#pragma unroll
            for (int nj = 0; nj < 2; nj++) {
                int keyrow = nj * 16 + (lane >> 4) * 8 + (lane & 7);
                uint32_t ko = (uint32_t)(keyrow * FQP + kcol * 2);
                ldm_x4(kh4[nj], sKh + ko);
                ldm_x4(kl4[nj], sKl + ko);
            }
            mma_bf16(sacc[0], qfh[kk], &kh4[0][0]);
            mma_bf16(sacc[1], qfh[kk], &kh4[0][2]);
            mma_bf16(sacc[2], qfh[kk], &kh4[1][0]);
            mma_bf16(sacc[3], qfh[kk], &kh4[1][2]);
            mma_bf16(sacc[0], qfh[kk], &kl4[0][0]);
            mma_bf16(sacc[1], qfh[kk], &kl4[0][2]);
            mma_bf16(sacc[2], qfh[kk], &kl4[1][0]);
            mma_bf16(sacc[3], qfh[kk], &kl4[1][2]);
            mma_bf16(sacc[0], qfl[kk], &kh4[0][0]);
            mma_bf16(sacc[1], qfl[kk], &kh4[0][2]);
            mma_bf16(sacc[2], qfl[kk], &kh4[1][0]);
            mma_bf16(sacc[3], qfl[kk], &kh4[1][2]);
        }

        // ---- online softmax (exp2 domain); l kept per-lane, reduced later ----
        float mA = -INFINITY, mB = -INFINITY;
#pragma unroll
        for (int nt = 0; nt < 4; nt++) {
            mA = fmaxf(mA, fmaxf(sacc[nt][0], sacc[nt][1]));
            mB = fmaxf(mB, fmaxf(sacc[nt][2], sacc[nt][3]));
        }
        mA = fmaxf(mA, __shfl_xor_sync(0xffffffffu, mA, 1));
        mA = fmaxf(mA, __shfl_xor_sync(0xffffffffu, mA, 2));
        mB = fmaxf(mB, __shfl_xor_sync(0xffffffffu, mB, 1));
        mB = fmaxf(mB, __shfl_xor_sync(0xffffffffu, mB, 2));

        float mnewA = fmaxf(mrunA, mA), mnewB = fmaxf(mrunB, mB);
        float alphaA = exp2f(mrunA - mnewA), alphaB = exp2f(mrunB - mnewB);
        mrunA = mnewA; mrunB = mnewB;

        uint32_t pfh[2][4], pfl[2][4];
        float sumA = 0.f, sumB = 0.f;
#pragma unroll
        for (int nt = 0; nt < 4; nt++) {
            float p0 = exp2f(sacc[nt][0] - mnewA);
            float p1 = exp2f(sacc[nt][1] - mnewA);
            float p2 = exp2f(sacc[nt][2] - mnewB);
            float p3 = exp2f(sacc[nt][3] - mnewB);
            sumA += p0 + p1; sumB += p2 + p3;
            __nv_bfloat16 h0 = __float2bfloat16(p0), h1 = __float2bfloat16(p1);
            __nv_bfloat16 h2 = __float2bfloat16(p2), h3 = __float2bfloat16(p3);
            int kk2 = nt >> 1, sl = (nt & 1) * 2;
            pfh[kk2][sl]     = pack2(h0, h1);
            pfh[kk2][sl + 1] = pack2(h2, h3);
            pfl[kk2][sl]     = pack2(__float2bfloat16(p0 - __bfloat162float(h0)),
                                     __float2bfloat16(p1 - __bfloat162float(h1)));
            pfl[kk2][sl + 1] = pack2(__float2bfloat16(p2 - __bfloat162float(h2)),
                                     __float2bfloat16(p3 - __bfloat162float(h3)));
        }
        // per-lane partial: alpha is quad-uniform, so this is exact
        lrunA = lrunA * alphaA + sumA;
        lrunB = lrunB * alphaB + sumB;

#pragma unroll
        for (int nt = 0; nt < 16; nt++) {
            oacc[nt][0] *= alphaA; oacc[nt][1] *= alphaA;
            oacc[nt][2] *= alphaB; oacc[nt][3] *= alphaB;
        }

        // ---- O += P @ V : dj pairs ----
#pragma unroll
        for (int kk2 = 0; kk2 < 2; kk2++) {
            const int keyrow = kk2 * 16 + (lane & 15);
#pragma unroll
            for (int djp = 0; djp < 4; djp++) {
                uint32_t vh4[2][4], vl4[2][4];
#pragma unroll
                for (int e = 0; e < 2; e++) {
                    int dcol = (djp * 2 + e) * 16 + (lane >> 4) * 8;
                    uint32_t vo = (uint32_t)(keyrow * FQP + dcol * 2);
                    ldm_x4t(vh4[e], sVh + vo);
                    ldm_x4t(vl4[e], sVl + vo);
                }
                float* o0 = oacc[4 * djp + 0];
                float* o1 = oacc[4 * djp + 1];
                float* o2 = oacc[4 * djp + 2];
                float* o3 = oacc[4 * djp + 3];
                mma_bf16(o0, pfh[kk2], &vh4[0][0]);
                mma_bf16(o1, pfh[kk2], &vh4[0][2]);
                mma_bf16(o2, pfh[kk2], &vh4[1][0]);
                mma_bf16(o3, pfh[kk2], &vh4[1][2]);
                mma_bf16(o0, pfh[kk2], &vl4[0][0]);
                mma_bf16(o1, pfh[kk2], &vl4[0][2]);
                mma_bf16(o2, pfh[kk2], &vl4[1][0]);
                mma_bf16(o3, pfh[kk2], &vl4[1][2]);
                mma_bf16(o0, pfl[kk2], &vh4[0][0]);
                mma_bf16(o1, pfl[kk2], &vh4[0][2]);
                mma_bf16(o2, pfl[kk2], &vh4[1][0]);
                mma_bf16(o3, pfl[kk2], &vh4[1][2]);
            }
        }

        buf  = (buf == 2) ? 0 : buf + 1;
        nbuf = (nbuf == 2) ? 0 : nbuf + 1;
    }

    // ---- epilogue: reduce l across the quad once, then normalize ----
    lrunA += __shfl_xor_sync(0xffffffffu, lrunA, 1);
    lrunA += __shfl_xor_sync(0xffffffffu, lrunA, 2);
    lrunB += __shfl_xor_sync(0xffffffffu, lrunB, 1);
    lrunB += __shfl_xor_sync(0xffffffffu, lrunB, 2);

    const float invA = 1.f / lrunA, invB = 1.f / lrunB;
    int rA = wr + (lane >> 2), rB = rA + 8;
    size_t gA = ((size_t)(bb * SS + m0 + rA)) * HID + h * HD;
    size_t gB = ((size_t)(bb * SS + m0 + rB)) * HID + h * HD;
#pragma unroll
    for (int nt = 0; nt < 16; nt++) {
        int col = nt * 8 + (lane & 3) * 2;
        float v0 = oacc[nt][0] * invA, v1 = oacc[nt][1] * invA;
        float v2 = oacc[nt][2] * invB, v3 = oacc[nt][3] * invB;
        __nv_bfloat16 h0 = __float2bfloat16(v0), h1 = __float2bfloat16(v1);
        __nv_bfloat16 h2 = __float2bfloat16(v2), h3 = __float2bfloat16(v3);
        *(__nv_bfloat162*)(ohi + gA + col) = __nv_bfloat162(h0, h1);
        *(__nv_bfloat162*)(ohi + gB + col) = __nv_bfloat162(h2, h3);
        *(__nv_bfloat162*)(olo + gA + col) = __nv_bfloat162(
            __float2bfloat16(v0 - __bfloat162float(h0)),
            __float2bfloat16(v1 - __bfloat162float(h1)));
        *(__nv_bfloat162*)(olo + gB + col) = __nv_bfloat162(
            __float2bfloat16(v2 - __bfloat162float(h2)),
            __float2bfloat16(v3 - __bfloat162float(h3)));
    }
}

// ---------------------------------------------------------------------------
// Launch
// ---------------------------------------------------------------------------
extern "C" void kernel_launch(void* const* d_in, const int* in_sizes, int n_in,
                              void* d_out, int out_size)
{
    const float* X  = (const float*)d_in[0];
    const float* Wq = (const float*)d_in[1];
    const float* bq = (const float*)d_in[2];
    const float* Wk = (const float*)d_in[3];
    const float* bk = (const float*)d_in[4];
    const float* Wv = (const float*)d_in[5];
    const float* bv = (const float*)d_in[6];
    const float* Wo = (const float*)d_in[7];
    const float* bo = (const float*)d_in[8];
    float* out = (float*)d_out;

    // 1/sqrt(128) * log2(e): softmax runs in exp2 domain
    const float qscale2 = 0.127517432f;

    __nv_bfloat16 *xh, *xl, *qh, *ql, *kh, *kl, *vh, *vl, *ah, *al;
    __nv_bfloat16 *wqh, *wql, *wkh, *wkl, *wvh, *wvl, *woh, *wol;
    cudaGetSymbolAddress((void**)&xh, g_xhi);  cudaGetSymbolAddress((void**)&xl, g_xlo);
    cudaGetSymbolAddress((void**)&qh, g_qhi);  cudaGetSymbolAddress((void**)&ql, g_qlo);
    cudaGetSymbolAddress((void**)&kh, g_khi);  cudaGetSymbolAddress((void**)&kl, g_klo);
    cudaGetSymbolAddress((void**)&vh, g_vhi);  cudaGetSymbolAddress((void**)&vl, g_vlo);
    cudaGetSymbolAddress((void**)&ah, g_ahi);  cudaGetSymbolAddress((void**)&al, g_alo);
    cudaGetSymbolAddress((void**)&wqh, g_wqh); cudaGetSymbolAddress((void**)&wql, g_wql);
    cudaGetSymbolAddress((void**)&wkh, g_wkh); cudaGetSymbolAddress((void**)&wkl, g_wkl);
    cudaGetSymbolAddress((void**)&wvh, g_wvh); cudaGetSymbolAddress((void**)&wvl, g_wvl);
    cudaGetSymbolAddress((void**)&woh, g_woh); cudaGetSymbolAddress((void**)&wol, g_wol);

    cudaFuncSetAttribute(gemm_qkv_kernel,
                         cudaFuncAttributeMaxDynamicSharedMemorySize, PROJ_SMEM);
    cudaFuncSetAttribute(gemm_o_kernel,
                         cudaFuncAttributeMaxDynamicSharedMemorySize, PROJ_SMEM);
    cudaFuncSetAttribute(mqa_mma_kernel,
                         cudaFuncAttributeMaxDynamicSharedMemorySize, FLASH_SMEM);

    // 1. all splits in one launch (scale folded into Wq)
    split_all_kernel<<<SPLIT_BLOCKS, 256>>>(
        X, Wq, Wk, Wv, Wo,
        xh, xl, wqh, wql, wkh, wkl, wvh, wvl, woh, wol, qscale2);

    // 2. fused Q+K+V projection (one launch, 576 CTAs, 128 threads)
    gemm_qkv_kernel<<<dim3(18, MROWS / 128), GTHREADS, PROJ_SMEM>>>(
        xh, xl,
        wqh, wql, bq, qscale2, qh, ql,
        wkh, wkl, bk, kh, kl,
        wvh, wvl, bv, vh, vl);

    // 3. flash attention (4-warp CTAs, 2/SM, 32-key tiles)
    mqa_mma_kernel<<<dim3(SS / 64, NH, BB), 128, FLASH_SMEM>>>(
        qh, ql, kh, kl, vh, vl, ah, al);

    // 4. output projection
    gemm_o_kernel<<<dim3(HID / 128, MROWS / 128), GTHREADS, PROJ_SMEM>>>(
        ah, al, woh, wol, bo, out);
}